// round 5
// baseline (speedup 1.0000x reference)
#include <cuda_runtime.h>
#include <float.h>
#include <math.h>
#include <stdint.h>

// Problem constants
#define NPTS 12288
#define DIM 64
#define KNN 16
#define EPS 1e-5f
#define DIAG_BIAS 1e6f

// Tiling: 256 threads, 2 CTAs/SM, 64x64 tiles, 4x4 per-thread (fp32x2 over k)
#define THREADS 256
#define BI 64
#define BJ 64
#define NSEG 3
#define SEGJ (NPTS / NSEG)        // 4096
#define NTILES (SEGJ / BJ)        // 64
#define NROWBLK (NPTS / BI)       // 192
#define KSTEPS (DIM / 2)          // 32

// smem layout (floats)
#define SI_STRIDE 132             // 64 rows * 2 + 4 pad
#define SJ_STRIDE 144             // 4 groups x (32 + 4 pad)
#define SD_STRIDE 68              // 64 + 4

#define SI_OFF   0
#define SJ_OFF   (KSTEPS * SI_STRIDE)                // 4224
#define SJ_BUF   (KSTEPS * SJ_STRIDE)                // 4608
#define SD_OFF   (SJ_OFF + 2 * SJ_BUF)               // 13440
#define SSQI_OFF (SD_OFF + BI * SD_STRIDE)           // 17792
#define SSQJ_OFF (SSQI_OFF + BI)                     // 17856 (2 x 64)
#define LV_OFF   (SSQJ_OFF + 2 * BJ)                 // 17984
#define LI_OFF   (LV_OFF + THREADS * KNN)            // 22080
#define SMEM_FLOATS (LI_OFF + (THREADS * KNN) / 2)   // 24128
#define SMEM_BYTES (SMEM_FLOATS * 4)                 // 96512

// Scratch (no allocations -> device globals)
__device__ float g_sq[NPTS];
__device__ float g_colsum[DIM];
__device__ float g_sigma_inv;
__device__ float g_vals[NPTS * NSEG * KNN];
__device__ int   g_idx [NPTS * NSEG * KNN];

typedef unsigned long long u64;

__device__ __forceinline__ u64 ffma2(u64 a, u64 b, u64 c) {
    u64 d;
    asm("fma.rn.f32x2 %0, %1, %2, %3;" : "=l"(d) : "l"(a), "l"(b), "l"(c));
    return d;
}
__device__ __forceinline__ float pairsum(u64 a) {
    float lo = __uint_as_float((unsigned)(a & 0xffffffffull));
    float hi = __uint_as_float((unsigned)(a >> 32));
    return lo + hi;
}
__device__ __forceinline__ uint32_t sptr(const void* p) {
    return (uint32_t)__cvta_generic_to_shared(p);
}
__device__ __forceinline__ void cp_async8(uint32_t dst, const void* src) {
    asm volatile("cp.async.ca.shared.global [%0], [%1], 8;" :: "r"(dst), "l"(src));
}
__device__ __forceinline__ void cp_async4(uint32_t dst, const void* src) {
    asm volatile("cp.async.ca.shared.global [%0], [%1], 4;" :: "r"(dst), "l"(src));
}
#define CP_COMMIT() asm volatile("cp.async.commit_group;")
#define CP_WAIT0()  asm volatile("cp.async.wait_group 0;")

// j-col c (0..63) -> float offset inside an sj row (grouped-padded, 2f/col)
__device__ __forceinline__ int jcol_off(int c) {
    return (c >> 4) * 36 + ((c >> 2) & 3) * 8 + (c & 3) * 2;
}

// ---------------------------------------------------------------------------
__global__ void sq_kernel(const float* __restrict__ coords) {
    int row = blockIdx.x * 256 + threadIdx.x;
    const float4* p = (const float4*)(coords + (size_t)row * DIM);
    float s = 0.f;
#pragma unroll
    for (int t = 0; t < DIM / 4; ++t) {
        float4 v = p[t];
        s += v.x * v.x + v.y * v.y + v.z * v.z + v.w * v.w;
    }
    g_sq[row] = s;
}

__global__ void colsum_kernel(const float* __restrict__ coords) {
    __shared__ float red[256];
    int d = blockIdx.x;
    float s = 0.f;
    for (int r = threadIdx.x; r < NPTS; r += 256)
        s += coords[(size_t)r * DIM + d];
    red[threadIdx.x] = s;
    __syncthreads();
    for (int off = 128; off > 0; off >>= 1) {
        if (threadIdx.x < off) red[threadIdx.x] += red[threadIdx.x + off];
        __syncthreads();
    }
    if (threadIdx.x == 0) g_colsum[d] = red[0];
}

__global__ void sigma_kernel() {
    __shared__ double red[256];
    double s = 0.0;
    for (int r = threadIdx.x; r < NPTS; r += 256)
        s += (double)g_sq[r];
    red[threadIdx.x] = s;
    __syncthreads();
    for (int off = 128; off > 0; off >>= 1) {
        if (threadIdx.x < off) red[threadIdx.x] += red[threadIdx.x + off];
        __syncthreads();
    }
    if (threadIdx.x == 0) {
        double sumsq = red[0];
        double nrm2 = 0.0;
        for (int d = 0; d < DIM; ++d) {
            double c = (double)g_colsum[d];
            nrm2 += c * c;
        }
        const double Nd = (double)NPTS;
        double total = 2.0 * Nd * sumsq - 2.0 * nrm2
                     + Nd * Nd * (double)EPS + Nd * (double)DIAG_BIAS;
        double sigma2 = total / (Nd * Nd);
        g_sigma_inv = (float)(1.0 / (sigma2 + (double)EPS));
    }
}

// register-array sorted insert (kernel C)
__device__ __forceinline__ void topk_insert(float (&vals)[KNN], int (&idx)[KNN],
                                            float v, int id) {
#pragma unroll
    for (int t = 0; t < KNN; ++t) {
        if (v < vals[t]) {
            float tv = vals[t]; vals[t] = v; v = tv;
            int   ti = idx[t];  idx[t]  = id; id = ti;
        }
    }
}

// smem sorted insert; caller guarantees v < lv[KNN-1] (rare path)
__device__ __forceinline__ void smem_insert(float* __restrict__ lv,
                                            unsigned short* __restrict__ li,
                                            float v, int id, float& thr) {
    int t = KNN - 1;
    while (t > 0) {
        float p = lv[t - 1];
        if (p <= v) break;
        lv[t] = p;
        li[t] = li[t - 1];
        --t;
    }
    lv[t] = v;
    li[t] = (unsigned short)id;
    thr = lv[KNN - 1];
}

// ---------------------------------------------------------------------------
// Stage one 64x64 j-tile (k-pair-major, grouped-padded) via cp.async.
// ---------------------------------------------------------------------------
__device__ __forceinline__ void issue_jtile(const float* __restrict__ coords,
                                            int jbase, float* sjb, float* ssqjb,
                                            int tid) {
#pragma unroll
    for (int u = 0; u < 8; ++u) {
        int e = u * THREADS + tid;       // 0..2047
        int s = e & 31;                  // k-pair
        int c = e >> 5;                  // j-col 0..63
        const float* src = coords + (size_t)(jbase + c) * DIM + 2 * s;
        float* dst = sjb + s * SJ_STRIDE + jcol_off(c);
        cp_async8(sptr(dst), src);
    }
    if (tid < BJ) cp_async4(sptr(ssqjb + tid), &g_sq[jbase + tid]);
}

// ---------------------------------------------------------------------------
// Kernel B: 64x64 distance tiles, 4x4 per-thread register tile (fp32x2),
// conflict-free smem layouts, cp.async double buffering, 2 CTAs/SM.
// ---------------------------------------------------------------------------
__global__ void __launch_bounds__(THREADS, 2)
knn5_kernel(const float* __restrict__ coords) {
    extern __shared__ float smem[];
    float* si   = smem + SI_OFF;
    float* sj   = smem + SJ_OFF;
    float* sd   = smem + SD_OFF;
    float* ssqi = smem + SSQI_OFF;
    float* ssqj = smem + SSQJ_OFF;

    const int tid  = threadIdx.x;
    const int ty   = tid >> 4;        // 0..15 -> rows ty*4..+3
    const int tx   = tid & 15;        // 0..15 -> cols tx*4..+3
    const int row0 = blockIdx.x * BI;
    const int jseg = blockIdx.y * SEGJ;

    // per-thread top-k list in smem, threshold in register
    float*          lv = smem + LV_OFF + tid * KNN;
    unsigned short* li = (unsigned short*)(smem + LI_OFF) + tid * KNN;
    float thr = FLT_MAX;
#pragma unroll
    for (int t = 0; t < KNN; ++t) { lv[t] = FLT_MAX; li[t] = 0; }

    // prologue: stage i-tile (plain k-pair-major) + j-tile 0 via cp.async
    {
#pragma unroll
        for (int u = 0; u < 8; ++u) {
            int e = u * THREADS + tid;   // 0..2047
            int s = e & 31;
            int r = e >> 5;              // i-row 0..63
            const float* src = coords + (size_t)(row0 + r) * DIM + 2 * s;
            float* dst = si + s * SI_STRIDE + r * 2;
            cp_async8(sptr(dst), src);
        }
        if (tid < BI) cp_async4(sptr(ssqi + tid), &g_sq[row0 + tid]);
        issue_jtile(coords, jseg, sj, ssqj, tid);
        CP_COMMIT();
    }

    const int bjoff = (tx >> 2) * 36 + (tx & 3) * 8;  // grouped-padded b addr
    const int srow  = tid >> 2;   // 0..63: row this thread scans
    const int squad = tid & 3;    // 16 cols each

    int buf = 0;
    for (int tile = 0; tile < NTILES; ++tile) {
        const int jbase = jseg + tile * BJ;
        CP_WAIT0();
        __syncthreads();           // sj[buf]+ssqj[buf] ready; sd scan done

        if (tile + 1 < NTILES) {
            issue_jtile(coords, jbase + BJ, sj + (buf ^ 1) * SJ_BUF,
                        ssqj + (buf ^ 1) * BJ, tid);
            CP_COMMIT();
        }

        // ---- compute 4x4 tile, packed fp32x2 over 32 k-steps ----
        u64 acc[4][4];
#pragma unroll
        for (int r = 0; r < 4; ++r)
#pragma unroll
            for (int c = 0; c < 4; ++c) acc[r][c] = 0ull;

        const float* aib = si + ty * 8;               // rows ty*4 (4 pairs)
        const float* sjb = sj + buf * SJ_BUF + bjoff;
#pragma unroll 8
        for (int s = 0; s < KSTEPS; ++s) {
            u64 ai[4], bj[4];
            {
                const ulonglong2* p = (const ulonglong2*)(aib + s * SI_STRIDE);
                ulonglong2 a0 = p[0], a1 = p[1];
                ai[0] = a0.x; ai[1] = a0.y; ai[2] = a1.x; ai[3] = a1.y;
            }
            {
                const ulonglong2* p = (const ulonglong2*)(sjb + s * SJ_STRIDE);
                ulonglong2 b0 = p[0], b1 = p[1];
                bj[0] = b0.x; bj[1] = b0.y; bj[2] = b1.x; bj[3] = b1.y;
            }
#pragma unroll
            for (int r = 0; r < 4; ++r)
#pragma unroll
                for (int c = 0; c < 4; ++c)
                    acc[r][c] = ffma2(ai[r], bj[c], acc[r][c]);
        }

        // ---- epilogue: distances -> sd ----
        {
            float sqj4[4];
#pragma unroll
            for (int c = 0; c < 4; ++c) sqj4[c] = ssqj[buf * BJ + tx * 4 + c];
#pragma unroll
            for (int r = 0; r < 4; ++r) {
                const int lr = ty * 4 + r;
                const int gr = row0 + lr;
                const float base = ssqi[lr] + EPS;
                float4 dv;
                float* dd = (float*)&dv;
#pragma unroll
                for (int c = 0; c < 4; ++c) {
                    float dot = pairsum(acc[r][c]);
                    float d = fmaf(-2.f, dot, base + sqj4[c]);
                    if (gr == jbase + tx * 4 + c) d += DIAG_BIAS;
                    dd[c] = d;
                }
                *(float4*)(sd + lr * SD_STRIDE + tx * 4) = dv;
            }
        }
        __syncthreads();

        // ---- streaming top-16: 4 threads per row, 16 cols each ----
        {
            const float* rp = sd + srow * SD_STRIDE + squad * 16;
            const int cbase = jbase + squad * 16;
#pragma unroll
            for (int c4 = 0; c4 < 4; ++c4) {
                float4 d = *(const float4*)(rp + c4 * 4);
                const int cb = cbase + c4 * 4;
                if (d.x < thr) smem_insert(lv, li, d.x, cb + 0, thr);
                if (d.y < thr) smem_insert(lv, li, d.y, cb + 1, thr);
                if (d.z < thr) smem_insert(lv, li, d.z, cb + 2, thr);
                if (d.w < thr) smem_insert(lv, li, d.w, cb + 3, thr);
            }
        }
        buf ^= 1;
    }

    // ---- merge the 4 quad lists per row, emit candidates ----
    __syncthreads();
    if (squad == 0) {
#pragma unroll
        for (int p = 1; p < 4; ++p) {
            const float*          pv = lv + p * KNN;
            const unsigned short* pi = li + p * KNN;
#pragma unroll
            for (int t = 0; t < KNN; ++t) {
                float c = pv[t];
                if (c < thr) smem_insert(lv, li, c, (int)pi[t], thr);
            }
        }
        const size_t o = ((size_t)(row0 + srow) * NSEG + blockIdx.y) * KNN;
#pragma unroll
        for (int t = 0; t < KNN; ++t) {
            g_vals[o + t] = lv[t];
            g_idx [o + t] = (int)li[t];
        }
    }
}

// ---------------------------------------------------------------------------
// Kernel C: merge NSEG candidate lists per row, compute Laplacian.
// ---------------------------------------------------------------------------
__global__ void merge_lap_kernel(const float* __restrict__ potential,
                                 float* __restrict__ out) {
    const int row = blockIdx.x * 256 + threadIdx.x;

    float vals[KNN];
    int   idx[KNN];
#pragma unroll
    for (int t = 0; t < KNN; ++t) { vals[t] = FLT_MAX; idx[t] = 0; }

    const size_t base = (size_t)row * NSEG * KNN;
    for (int s = 0; s < NSEG; ++s) {
#pragma unroll
        for (int kk = 0; kk < KNN; ++kk) {
            float c = g_vals[base + s * KNN + kk];
            if (c < vals[KNN - 1]) topk_insert(vals, idx, c, g_idx[base + s * KNN + kk]);
        }
    }

    const float inv = g_sigma_inv;
    const float vi  = potential[row];
    float lap = 0.f;
#pragma unroll
    for (int t = 0; t < KNN; ++t) {
        float w = expf(-vals[t] * inv);
        lap += w * (potential[idx[t]] - vi);
    }
    out[row] = lap;
}

// ---------------------------------------------------------------------------
extern "C" void kernel_launch(void* const* d_in, const int* in_sizes, int n_in,
                              void* d_out, int out_size) {
    const float* coords    = (const float*)d_in[0];
    const float* potential = (const float*)d_in[1];
    float* out = (float*)d_out;

    cudaFuncSetAttribute(knn5_kernel,
                         cudaFuncAttributeMaxDynamicSharedMemorySize,
                         SMEM_BYTES);

    sq_kernel<<<NPTS / 256, 256>>>(coords);
    colsum_kernel<<<DIM, 256>>>(coords);
    sigma_kernel<<<1, 256>>>();

    dim3 grid(NROWBLK, NSEG);
    knn5_kernel<<<grid, THREADS, SMEM_BYTES>>>(coords);

    merge_lap_kernel<<<NPTS / 256, 256>>>(potential, out);
}

// round 9
// speedup vs baseline: 1.0173x; 1.0173x over previous
#include <cuda_runtime.h>
#include <float.h>
#include <math.h>
#include <stdint.h>

// Problem constants
#define NPTS 12288
#define DIM 64
#define KNN 16
#define KP  20                    // padded candidate list depth
#define EPS 1e-5f
#define DIAG_BIAS 1e6f

// Tiling: 256 threads (8 warps x m16), BI=128 rows, BJ=32 cols per tile
#define THREADS 256
#define BI 128
#define BJ 32
#define NSEG 3
#define SEGJ (NPTS / NSEG)        // 4096
#define NTILES (SEGJ / BJ)        // 128
#define NROWBLK (NPTS / BI)       // 96
#define NCAND (NSEG * KP)         // 60 candidates per row

// smem layout (floats). sj holds (hi,lo)-interleaved j-tiles: [col][k][2].
#define SJ_STRIDE 136
#define SJ_BUF (BJ * SJ_STRIDE)                      // 4352
#define SSQJ_OFF (2 * SJ_BUF)                        // 8704
#define LV_OFF (SSQJ_OFF + 2 * BJ)                   // 8768
#define LI_OFF (LV_OFF + THREADS * 2 * KP)           // 19008
#define SMEM_FLOATS (LI_OFF + (THREADS * 2 * KP) / 2) // 24128
#define SMEM_BYTES (SMEM_FLOATS * 4)                 // 96512

// Scratch (no allocations -> device globals)
__device__ float g_pair[NPTS * DIM * 2];   // (hi,lo) interleaved per element
__device__ float g_sq[NPTS];
__device__ float g_colsum[DIM];
__device__ float g_sigma_inv;
__device__ float g_vals[NPTS * NSEG * KP];
__device__ int   g_idx [NPTS * NSEG * KP];

typedef unsigned long long u64;

__device__ __forceinline__ uint32_t sptr(const void* p) {
    return (uint32_t)__cvta_generic_to_shared(p);
}
__device__ __forceinline__ void cp_async16(uint32_t dst, const void* src) {
    asm volatile("cp.async.cg.shared.global [%0], [%1], 16;" :: "r"(dst), "l"(src));
}
__device__ __forceinline__ void cp_async4(uint32_t dst, const void* src) {
    asm volatile("cp.async.ca.shared.global [%0], [%1], 4;" :: "r"(dst), "l"(src));
}
#define CP_COMMIT() asm volatile("cp.async.commit_group;")
#define CP_WAIT0()  asm volatile("cp.async.wait_group 0;")

// packed fp32x2 fma (same instruction R2 used for its exact scoring)
__device__ __forceinline__ u64 ffma2(u64 a, u64 b, u64 c) {
    u64 d;
    asm("fma.rn.f32x2 %0, %1, %2, %3;" : "=l"(d) : "l"(a), "l"(b), "l"(c));
    return d;
}
__device__ __forceinline__ float pairsum(u64 a) {
    float lo = __uint_as_float((unsigned)(a & 0xffffffffull));
    float hi = __uint_as_float((unsigned)(a >> 32));
    return lo + hi;
}

// m16n8k8 tf32 mma: D = A*B + D (row-major A, col-major B), fp32 accum
__device__ __forceinline__ void mma_tf32(float (&c)[4], const uint32_t* a,
                                         uint32_t b0, uint32_t b1) {
    asm volatile(
        "mma.sync.aligned.m16n8k8.row.col.f32.tf32.tf32.f32 "
        "{%0,%1,%2,%3}, {%4,%5,%6,%7}, {%8,%9}, {%0,%1,%2,%3};"
        : "+f"(c[0]), "+f"(c[1]), "+f"(c[2]), "+f"(c[3])
        : "r"(a[0]), "r"(a[1]), "r"(a[2]), "r"(a[3]), "r"(b0), "r"(b1));
}

// ---------------------------------------------------------------------------
// Prologue: split coords into (hi = tf32-rounded, lo = x - hi), interleaved.
// ---------------------------------------------------------------------------
__global__ void split_kernel(const float* __restrict__ coords) {
    int i = blockIdx.x * 256 + threadIdx.x;   // 0 .. NPTS*DIM-1
    float x = coords[i];
    uint32_t h;
    asm("cvt.rna.tf32.f32 %0, %1;" : "=r"(h) : "f"(x));
    float hf = __uint_as_float(h);
    float2 p = make_float2(hf, x - hf);
    *(float2*)&g_pair[2 * i] = p;
}

// ---------------------------------------------------------------------------
__global__ void sq_kernel(const float* __restrict__ coords) {
    int row = blockIdx.x * 256 + threadIdx.x;
    const float4* p = (const float4*)(coords + (size_t)row * DIM);
    float s = 0.f;
#pragma unroll
    for (int t = 0; t < DIM / 4; ++t) {
        float4 v = p[t];
        s += v.x * v.x + v.y * v.y + v.z * v.z + v.w * v.w;
    }
    g_sq[row] = s;
}

__global__ void colsum_kernel(const float* __restrict__ coords) {
    __shared__ float red[256];
    int d = blockIdx.x;
    float s = 0.f;
    for (int r = threadIdx.x; r < NPTS; r += 256)
        s += coords[(size_t)r * DIM + d];
    red[threadIdx.x] = s;
    __syncthreads();
    for (int off = 128; off > 0; off >>= 1) {
        if (threadIdx.x < off) red[threadIdx.x] += red[threadIdx.x + off];
        __syncthreads();
    }
    if (threadIdx.x == 0) g_colsum[d] = red[0];
}

__global__ void sigma_kernel() {
    __shared__ double red[256];
    double s = 0.0;
    for (int r = threadIdx.x; r < NPTS; r += 256)
        s += (double)g_sq[r];
    red[threadIdx.x] = s;
    __syncthreads();
    for (int off = 128; off > 0; off >>= 1) {
        if (threadIdx.x < off) red[threadIdx.x] += red[threadIdx.x + off];
        __syncthreads();
    }
    if (threadIdx.x == 0) {
        double sumsq = red[0];
        double nrm2 = 0.0;
        for (int d = 0; d < DIM; ++d) {
            double c = (double)g_colsum[d];
            nrm2 += c * c;
        }
        const double Nd = (double)NPTS;
        double total = 2.0 * Nd * sumsq - 2.0 * nrm2
                     + Nd * Nd * (double)EPS + Nd * (double)DIAG_BIAS;
        double sigma2 = total / (Nd * Nd);
        g_sigma_inv = (float)(1.0 / (sigma2 + (double)EPS));
    }
}

// lexicographic (value, index) sorted insert: on equal values the lower
// index ranks first -- matches jax.lax.top_k tie semantics and R2's
// streaming-order selection.
__device__ __forceinline__ void topk_insert_tie(float (&vals)[KNN],
                                                int (&idx)[KNN],
                                                float v, int id) {
#pragma unroll
    for (int t = 0; t < KNN; ++t) {
        bool lt = (v < vals[t]) || (v == vals[t] && id < idx[t]);
        if (lt) {
            float tv = vals[t]; vals[t] = v; v = tv;
            int   ti = idx[t];  idx[t]  = id; id = ti;
        }
    }
}

// smem sorted insert (KP-deep); caller guarantees v < lv[KP-1] (rare path)
__device__ __forceinline__ void smem_insert(float* __restrict__ lv,
                                            unsigned short* __restrict__ li,
                                            float v, int id, float& thr) {
    int t = KP - 1;
    while (t > 0) {
        float p = lv[t - 1];
        if (p <= v) break;
        lv[t] = p;
        li[t] = li[t - 1];
        --t;
    }
    lv[t] = v;
    li[t] = (unsigned short)id;
    thr = lv[KP - 1];
}

// ---------------------------------------------------------------------------
// Stage one 32-row j-tile (512B per row, direct copy of g_pair rows).
// ---------------------------------------------------------------------------
__device__ __forceinline__ void issue_jtile(int jbase, float* sjb,
                                            float* ssqjb, int tid) {
    int r = tid >> 3;        // 0..31 tile row
    int q = tid & 7;
    const float* src = g_pair + (size_t)(jbase + r) * (DIM * 2);
    float* dst = sjb + r * SJ_STRIDE;
#pragma unroll
    for (int m = 0; m < 4; ++m) {
        int ch = q + m * 8;  // 16B chunk 0..31
        cp_async16(sptr(dst + ch * 4), src + ch * 4);
    }
    if (tid < BJ) cp_async4(sptr(ssqjb + tid), &g_sq[jbase + tid]);
}

// ---------------------------------------------------------------------------
// Kernel B: tensor-core distance tiles + in-register streaming top-KP.
// Split-TF32 (3 MMA) candidate selection; exact rescore happens downstream.
// ---------------------------------------------------------------------------
__global__ void __launch_bounds__(THREADS, 2)
knn_mma_kernel() {
    extern __shared__ float smem[];
    float* sj   = smem;
    float* ssqj = smem + SSQJ_OFF;

    const int tid = threadIdx.x;
    const int w = tid >> 5, l = tid & 31;
    const int g = l >> 2, t = l & 3;
    const int row0 = blockIdx.x * BI;
    const int jseg = blockIdx.y * SEGJ;
    const int rowA0 = row0 + w * 16 + g;
    const int rowA1 = rowA0 + 8;

    float*          lv0 = smem + LV_OFF + (tid * 2 + 0) * KP;
    float*          lv1 = smem + LV_OFF + (tid * 2 + 1) * KP;
    unsigned short* li0 = (unsigned short*)(smem + LI_OFF) + (tid * 2 + 0) * KP;
    unsigned short* li1 = (unsigned short*)(smem + LI_OFF) + (tid * 2 + 1) * KP;
    float thr0 = FLT_MAX, thr1 = FLT_MAX;
#pragma unroll
    for (int k = 0; k < KP; ++k) {
        lv0[k] = FLT_MAX; lv1[k] = FLT_MAX; li0[k] = 0; li1[k] = 0;
    }

    // A fragments (persistent): hi and lo, 8 k-chunks x 4 regs each
    uint32_t ah[32], al[32];
#pragma unroll
    for (int kc = 0; kc < 8; ++kc) {
        float2 p;
        p = *(const float2*)&g_pair[(size_t)(rowA0 * DIM + kc * 8 + t) * 2];
        ah[kc * 4 + 0] = __float_as_uint(p.x); al[kc * 4 + 0] = __float_as_uint(p.y);
        p = *(const float2*)&g_pair[(size_t)(rowA1 * DIM + kc * 8 + t) * 2];
        ah[kc * 4 + 1] = __float_as_uint(p.x); al[kc * 4 + 1] = __float_as_uint(p.y);
        p = *(const float2*)&g_pair[(size_t)(rowA0 * DIM + kc * 8 + t + 4) * 2];
        ah[kc * 4 + 2] = __float_as_uint(p.x); al[kc * 4 + 2] = __float_as_uint(p.y);
        p = *(const float2*)&g_pair[(size_t)(rowA1 * DIM + kc * 8 + t + 4) * 2];
        ah[kc * 4 + 3] = __float_as_uint(p.x); al[kc * 4 + 3] = __float_as_uint(p.y);
    }
    const float sqi0 = g_sq[rowA0];
    const float sqi1 = g_sq[rowA1];

    issue_jtile(jseg, sj, ssqj, tid);
    CP_COMMIT();

    int buf = 0;
    for (int tile = 0; tile < NTILES; ++tile) {
        const int jbase = jseg + tile * BJ;
        CP_WAIT0();
        __syncthreads();

        if (tile + 1 < NTILES) {
            issue_jtile(jbase + BJ, sj + (buf ^ 1) * SJ_BUF,
                        ssqj + (buf ^ 1) * BJ, tid);
            CP_COMMIT();
        }

        const float* sjb = sj + buf * SJ_BUF;
#pragma unroll
        for (int nt2 = 0; nt2 < 2; ++nt2) {
            float c0[4] = {0.f, 0.f, 0.f, 0.f};
            float c1[4] = {0.f, 0.f, 0.f, 0.f};
            const float* b0p = sjb + (nt2 * 16 + g) * SJ_STRIDE + t * 2;
            const float* b1p = sjb + (nt2 * 16 + 8 + g) * SJ_STRIDE + t * 2;
#pragma unroll
            for (int kc = 0; kc < 8; ++kc) {
                float2 x0 = *(const float2*)(b0p + kc * 16);
                float2 x4 = *(const float2*)(b0p + kc * 16 + 8);
                float2 y0 = *(const float2*)(b1p + kc * 16);
                float2 y4 = *(const float2*)(b1p + kc * 16 + 8);
                mma_tf32(c0, ah + kc * 4, __float_as_uint(x0.x), __float_as_uint(x4.x));
                mma_tf32(c0, ah + kc * 4, __float_as_uint(x0.y), __float_as_uint(x4.y));
                mma_tf32(c0, al + kc * 4, __float_as_uint(x0.x), __float_as_uint(x4.x));
                mma_tf32(c1, ah + kc * 4, __float_as_uint(y0.x), __float_as_uint(y4.x));
                mma_tf32(c1, ah + kc * 4, __float_as_uint(y0.y), __float_as_uint(y4.y));
                mma_tf32(c1, al + kc * 4, __float_as_uint(y0.x), __float_as_uint(y4.x));
            }
#pragma unroll
            for (int h = 0; h < 2; ++h) {
                const float* c = h ? c1 : c0;
                const int nt = nt2 * 2 + h;
                const int colb = nt * 8 + 2 * t;
                const float sqj0 = ssqj[buf * BJ + colb];
                const float sqj1 = ssqj[buf * BJ + colb + 1];
                const int col0 = jbase + colb, col1 = col0 + 1;
                float d0 = fmaf(-2.f, c[0], sqi0 + sqj0 + EPS);
                float d1 = fmaf(-2.f, c[1], sqi0 + sqj1 + EPS);
                float d2 = fmaf(-2.f, c[2], sqi1 + sqj0 + EPS);
                float d3 = fmaf(-2.f, c[3], sqi1 + sqj1 + EPS);
                if (rowA0 == col0) d0 += DIAG_BIAS;
                if (rowA0 == col1) d1 += DIAG_BIAS;
                if (rowA1 == col0) d2 += DIAG_BIAS;
                if (rowA1 == col1) d3 += DIAG_BIAS;
                if (d0 < thr0) smem_insert(lv0, li0, d0, col0, thr0);
                if (d1 < thr0) smem_insert(lv0, li0, d1, col1, thr0);
                if (d2 < thr1) smem_insert(lv1, li1, d2, col0, thr1);
                if (d3 < thr1) smem_insert(lv1, li1, d3, col1, thr1);
            }
        }
        buf ^= 1;
    }

    // ---- merge the 4 t-lane lists per row, emit per-segment candidates ----
    __syncthreads();
    if (t == 0) {
#pragma unroll
        for (int p = 1; p < 4; ++p) {
            const float*          pv = lv0 + p * 2 * KP;
            const unsigned short* pi = li0 + p * 2 * KP;
#pragma unroll
            for (int k = 0; k < KP; ++k) {
                float c = pv[k];
                if (c < thr0) smem_insert(lv0, li0, c, (int)pi[k], thr0);
            }
            const float*          qv = lv1 + p * 2 * KP;
            const unsigned short* qi = li1 + p * 2 * KP;
#pragma unroll
            for (int k = 0; k < KP; ++k) {
                float c = qv[k];
                if (c < thr1) smem_insert(lv1, li1, c, (int)qi[k], thr1);
            }
        }
        const size_t o0 = ((size_t)rowA0 * NSEG + blockIdx.y) * KP;
        const size_t o1 = ((size_t)rowA1 * NSEG + blockIdx.y) * KP;
#pragma unroll
        for (int k = 0; k < KP; ++k) {
            g_vals[o0 + k] = lv0[k];
            g_idx [o0 + k] = (int)li0[k];
            g_vals[o1 + k] = lv1[k];
            g_idx [o1 + k] = (int)li1[k];
        }
    }
}

// ---------------------------------------------------------------------------
// Kernel C: rescore the 60 candidates per row with R2's EXACT arithmetic
// (ffma2 even/odd-pair chain, pairsum lo+hi, d = fma(-2, dot, (sqi+EPS)+sqj)),
// select top-16 with lexicographic (value, index) tie-break, compute Laplacian.
// This bit-reproduces the R2 kernel's selection and weights (rel_err 8.5e-8).
// ---------------------------------------------------------------------------
__global__ void __launch_bounds__(128)
rescore_lap_kernel(const float* __restrict__ coords,
                   const float* __restrict__ potential,
                   float* __restrict__ out) {
    const int row = blockIdx.x * 128 + threadIdx.x;

    // load x_i as (even,odd) dim pairs
    u64 xi2[DIM / 2];
    {
        const u64* p = (const u64*)(coords + (size_t)row * DIM);
#pragma unroll
        for (int s = 0; s < DIM / 2; ++s) xi2[s] = p[s];
    }
    const float sqi = g_sq[row];
    const float base_i = sqi + EPS;          // R2: base = ssqi + EPS

    float vals[KNN];
    int   idx[KNN];
#pragma unroll
    for (int t = 0; t < KNN; ++t) { vals[t] = FLT_MAX; idx[t] = 0x7fffffff; }

    const size_t cbase = (size_t)row * NCAND;
#pragma unroll 2
    for (int c = 0; c < NCAND; ++c) {
        const int j = g_idx[cbase + c];
        const ulonglong2* xj = (const ulonglong2*)(coords + (size_t)j * DIM);
        u64 acc = 0ull;
#pragma unroll
        for (int s = 0; s < DIM / 2; s += 2) {
            ulonglong2 v = xj[s >> 1];
            acc = ffma2(xi2[s], v.x, acc);
            acc = ffma2(xi2[s + 1], v.y, acc);
        }
        const float dot = pairsum(acc);
        const float d = fmaf(-2.f, dot, base_i + g_sq[j]);   // R2 rounding order
        if (d < vals[KNN - 1] || (d == vals[KNN - 1] && j < idx[KNN - 1]))
            topk_insert_tie(vals, idx, d, j);
    }

    const float inv = g_sigma_inv;
    const float vi  = potential[row];
    float lap = 0.f;
#pragma unroll
    for (int t = 0; t < KNN; ++t) {
        float w = expf(-vals[t] * inv);
        lap += w * (potential[idx[t]] - vi);
    }
    out[row] = lap;
}

// ---------------------------------------------------------------------------
extern "C" void kernel_launch(void* const* d_in, const int* in_sizes, int n_in,
                              void* d_out, int out_size) {
    const float* coords    = (const float*)d_in[0];
    const float* potential = (const float*)d_in[1];
    float* out = (float*)d_out;

    cudaFuncSetAttribute(knn_mma_kernel,
                         cudaFuncAttributeMaxDynamicSharedMemorySize,
                         SMEM_BYTES);

    sq_kernel<<<NPTS / 256, 256>>>(coords);
    split_kernel<<<NPTS * DIM / 256, 256>>>(coords);
    colsum_kernel<<<DIM, 256>>>(coords);
    sigma_kernel<<<1, 256>>>();

    dim3 grid(NROWBLK, NSEG);
    knn_mma_kernel<<<grid, THREADS, SMEM_BYTES>>>();

    rescore_lap_kernel<<<NPTS / 128, 128>>>(coords, potential, out);
}